// round 9
// baseline (speedup 1.0000x reference)
#include <cuda_runtime.h>

// out[row] = sum_l in[row*1024 + l] / (l+1),  rows = 131072, L = 1024.
//
// R9: R8's static one-wave schedule + 4-row joint reduction.
//  - 9 shuffles per 4 rows (vs 12): per-row cross-half shfl16, merge pairs at
//    shfl8 with select, shared 3-step butterfly. Final sums land in lanes
//    0/8/16/24 -> 4 writes into the same 32B output sector.
//  - Row-granular balanced split (quad-granular would double warp imbalance);
//    remainder rows use the 2-row then 1-row reductions.
// Evidence so far: three schedules plateau at 6.45-6.63 TB/s ~= LTS cap
// (6300 B/cyc) at NAT clock; only serial per-row overhead is still winnable.

static constexpr int L       = 1024;
static constexpr int ROWS    = 4 * 8 * 4096;   // 131072
static constexpr int THREADS = 256;            // 8 warps
static constexpr int GRID    = 152 * 5;        // one full wave at 5 blocks/SM

__device__ __forceinline__ float row_partial(const float* __restrict__ in,
                                             const float4* __restrict__ w4,
                                             int lane, int row) {
    const float4* p = reinterpret_cast<const float4*>(in + (size_t)row * L) + lane;

    // Front-batch 8 loads (MLP=8 per warp), read-once streaming.
    float4 v[8];
    #pragma unroll
    for (int k = 0; k < 8; k++) {
        v[k] = __ldcs(p + k * 32);   // warp stride = 32 float4 = 128 floats
    }

    float s0 = 0.0f, s1 = 0.0f;
    #pragma unroll
    for (int k = 0; k < 8; k++) {
        float4 w = w4[lane + 32 * k];
        s0 = fmaf(v[k].x, w.x, s0);
        s1 = fmaf(v[k].y, w.y, s1);
        s0 = fmaf(v[k].z, w.z, s0);
        s1 = fmaf(v[k].w, w.w, s1);
    }
    return s0 + s1;
}

__global__ __launch_bounds__(THREADS, 5)
void fractal_dim_kernel(const float* __restrict__ in, float* __restrict__ out) {
    __shared__ float4 w4[L / 4];   // w4[i] = {1/(4i+1), ..., 1/(4i+4)}

    const int t = threadIdx.x;
    {
        int base = t * 4;
        float4 w;
        w.x = 1.0f / (float)(base + 1);
        w.y = 1.0f / (float)(base + 2);
        w.z = 1.0f / (float)(base + 3);
        w.w = 1.0f / (float)(base + 4);
        w4[t] = w;
    }
    __syncthreads();

    const int lane = t & 31;
    const int wid  = t >> 5;

    // Balanced contiguous split: block range, then warp range within it.
    const int bstart = (int)((long long)blockIdx.x       * ROWS / GRID);
    const int bend   = (int)((long long)(blockIdx.x + 1) * ROWS / GRID);
    const int n      = bend - bstart;
    const int wstart = bstart + (int)((long long)wid       * n / 8);
    const int wend   = bstart + (int)((long long)(wid + 1) * n / 8);

    int row = wstart;

    // ── 4-row batches: 9-shuffle joint reduction ──
    for (; row + 3 < wend; row += 4) {
        float sA = row_partial(in, w4, lane, row);
        float sB = row_partial(in, w4, lane, row + 1);
        float sC = row_partial(in, w4, lane, row + 2);
        float sD = row_partial(in, w4, lane, row + 3);

        // Stage 1: cross-half exchange, pack A|B and C|D across halves.
        float xa = sA + __shfl_xor_sync(0xffffffffu, sA, 16);
        float xb = sB + __shfl_xor_sync(0xffffffffu, sB, 16);
        float xc = sC + __shfl_xor_sync(0xffffffffu, sC, 16);
        float xd = sD + __shfl_xor_sync(0xffffffffu, sD, 16);
        float z1 = (lane < 16) ? xa : xb;   // A in lanes 0-15, B in 16-31
        float z2 = (lane < 16) ? xc : xd;   // C in lanes 0-15, D in 16-31

        // Stage 2: fold at offset 8, interleave quads: A|C|B|D per 8 lanes.
        float t1 = z1 + __shfl_xor_sync(0xffffffffu, z1, 8);
        float t2 = z2 + __shfl_xor_sync(0xffffffffu, z2, 8);
        float w  = (lane & 8) ? t2 : t1;

        // Stage 3: shared butterfly over the 8-lane groups.
        #pragma unroll
        for (int off = 4; off > 0; off >>= 1) {
            w += __shfl_xor_sync(0xffffffffu, w, off);
        }

        // lanes 0/8/16/24 hold rows A/C/B/D — same 32B sector in out[].
        if (lane == 0)  out[row]     = w;
        if (lane == 8)  out[row + 2] = w;
        if (lane == 16) out[row + 1] = w;
        if (lane == 24) out[row + 3] = w;
    }

    // ── 2-row remainder ──
    for (; row + 1 < wend; row += 2) {
        float sA = row_partial(in, w4, lane, row);
        float sB = row_partial(in, w4, lane, row + 1);

        float xa = sA + __shfl_xor_sync(0xffffffffu, sA, 16);
        float xb = sB + __shfl_xor_sync(0xffffffffu, sB, 16);
        float z  = (lane < 16) ? xa : xb;

        #pragma unroll
        for (int off = 8; off > 0; off >>= 1) {
            z += __shfl_xor_sync(0xffffffffu, z, off);
        }

        if (lane == 0)  out[row]     = z;
        if (lane == 16) out[row + 1] = z;
    }

    // ── Possible odd final row ──
    if (row < wend) {
        float s = row_partial(in, w4, lane, row);
        #pragma unroll
        for (int off = 16; off > 0; off >>= 1) {
            s += __shfl_xor_sync(0xffffffffu, s, off);
        }
        if (lane == 0) out[row] = s;
    }
}

extern "C" void kernel_launch(void* const* d_in, const int* in_sizes, int n_in,
                              void* d_out, int out_size) {
    const float* in  = (const float*)d_in[0];
    float*       out = (float*)d_out;
    fractal_dim_kernel<<<GRID, THREADS>>>(in, out);
}

// round 10
// speedup vs baseline: 1.0269x; 1.0269x over previous
#include <cuda_runtime.h>

// out[row] = sum_l in[row*1024 + l] / (l+1),  rows = 131072, L = 1024.
//
// FINAL (= R8, best verified at 81.9us / 6630 GB/s = 83% of HBM spec):
//  - One resident wave: 760 blocks (152 SMs x 5), balanced contiguous
//    per-warp row ranges (static; dynamic queues regressed in R6/R7).
//  - Weights 1/(l+1) in 4KB smem, computed once per block (keeps regs at 48,
//    occupancy ~60%).
//  - Per row: 8 front-batched float4 __ldcs loads (MLP=8; this exact issue
//    pattern is load-bearing — 4-row batching in R9 broke it and lost 6%).
//  - Rows processed in pairs with a 6-shuffle joint reduction; lanes 0/16
//    write the two results.
// Plateau across 7 variants at ~6.5-6.6 TB/s ~= B300 LTS path cap
// (~6300 B/cyc) at this kernel's NAT clock -> memory-path roofline reached.

static constexpr int L       = 1024;
static constexpr int ROWS    = 4 * 8 * 4096;   // 131072
static constexpr int THREADS = 256;            // 8 warps
static constexpr int GRID    = 152 * 5;        // one full wave at 5 blocks/SM

__device__ __forceinline__ float row_partial(const float* __restrict__ in,
                                             const float4* __restrict__ w4,
                                             int lane, int row) {
    const float4* p = reinterpret_cast<const float4*>(in + (size_t)row * L) + lane;

    // Front-batch 8 loads (MLP=8 per warp), read-once streaming.
    float4 v[8];
    #pragma unroll
    for (int k = 0; k < 8; k++) {
        v[k] = __ldcs(p + k * 32);   // warp stride = 32 float4 = 128 floats
    }

    float s0 = 0.0f, s1 = 0.0f;
    #pragma unroll
    for (int k = 0; k < 8; k++) {
        float4 w = w4[lane + 32 * k];
        s0 = fmaf(v[k].x, w.x, s0);
        s1 = fmaf(v[k].y, w.y, s1);
        s0 = fmaf(v[k].z, w.z, s0);
        s1 = fmaf(v[k].w, w.w, s1);
    }
    return s0 + s1;
}

__global__ __launch_bounds__(THREADS, 5)
void fractal_dim_kernel(const float* __restrict__ in, float* __restrict__ out) {
    __shared__ float4 w4[L / 4];   // w4[i] = {1/(4i+1), ..., 1/(4i+4)}

    const int t = threadIdx.x;
    {
        int base = t * 4;
        float4 w;
        w.x = 1.0f / (float)(base + 1);
        w.y = 1.0f / (float)(base + 2);
        w.z = 1.0f / (float)(base + 3);
        w.w = 1.0f / (float)(base + 4);
        w4[t] = w;
    }
    __syncthreads();

    const int lane = t & 31;
    const int wid  = t >> 5;

    // Balanced contiguous split: block range, then warp range within it.
    const int bstart = (int)((long long)blockIdx.x       * ROWS / GRID);
    const int bend   = (int)((long long)(blockIdx.x + 1) * ROWS / GRID);
    const int n      = bend - bstart;
    const int wstart = bstart + (int)((long long)wid       * n / 8);
    const int wend   = bstart + (int)((long long)(wid + 1) * n / 8);

    int row = wstart;

    // ── Paired rows: 6-shuffle joint reduction ──
    for (; row + 1 < wend; row += 2) {
        float sA = row_partial(in, w4, lane, row);
        float sB = row_partial(in, w4, lane, row + 1);

        // Cross-half exchange, then select A into lanes 0-15, B into 16-31.
        float xa = sA + __shfl_xor_sync(0xffffffffu, sA, 16);
        float xb = sB + __shfl_xor_sync(0xffffffffu, sB, 16);
        float z  = (lane < 16) ? xa : xb;

        #pragma unroll
        for (int off = 8; off > 0; off >>= 1) {
            z += __shfl_xor_sync(0xffffffffu, z, off);
        }

        if (lane == 0)  out[row]     = z;   // full sum of row A
        if (lane == 16) out[row + 1] = z;   // full sum of row B
    }

    // ── Possible odd final row ──
    if (row < wend) {
        float s = row_partial(in, w4, lane, row);
        #pragma unroll
        for (int off = 16; off > 0; off >>= 1) {
            s += __shfl_xor_sync(0xffffffffu, s, off);
        }
        if (lane == 0) out[row] = s;
    }
}

extern "C" void kernel_launch(void* const* d_in, const int* in_sizes, int n_in,
                              void* d_out, int out_size) {
    const float* in  = (const float*)d_in[0];
    float*       out = (float*)d_out;
    fractal_dim_kernel<<<GRID, THREADS>>>(in, out);
}

// round 12
// speedup vs baseline: 1.0496x; 1.0221x over previous
#include <cuda_runtime.h>

// out[row] = sum_l in[row*1024 + l] / (l+1),  rows = 131072, L = 1024.
//
// FINAL (R8 structure; best verified 81.9us / 6630 GB/s = 83% of HBM spec;
// identical source re-measured at 84.5us -> run-to-run variance ±3% exceeds
// all remaining headroom):
//  - One resident wave: 760 blocks (152 SMs x 5), balanced contiguous
//    per-warp row ranges. Static schedule: dynamic queues (R6/R7) lost
//    8-12%; 4-row batching (R9) broke the front-batched load pattern and
//    lost 6%.
//  - Weights 1/(l+1) in 4KB smem, computed once per block (regs=48,
//    occ ~60%; occupancy beyond ~50% measurably does not raise DRAM%).
//  - Per row: 8 front-batched float4 __ldcs loads (MLP=8) — this exact
//    issue pattern is load-bearing.
//  - Rows in pairs, 6-shuffle joint reduction; lanes 0/16 write.
// Plateau 6.45-6.63 TB/s across all healthy variants ~= B300 LTS path cap
// (~6300 B/cyc, path-independent) at this kernel's clock: roofline reached.

static constexpr int L       = 1024;
static constexpr int ROWS    = 4 * 8 * 4096;   // 131072
static constexpr int THREADS = 256;            // 8 warps
static constexpr int GRID    = 152 * 5;        // one full wave at 5 blocks/SM

__device__ __forceinline__ float row_partial(const float* __restrict__ in,
                                             const float4* __restrict__ w4,
                                             int lane, int row) {
    const float4* p = reinterpret_cast<const float4*>(in + (size_t)row * L) + lane;

    // Front-batch 8 loads (MLP=8 per warp), read-once streaming.
    float4 v[8];
    #pragma unroll
    for (int k = 0; k < 8; k++) {
        v[k] = __ldcs(p + k * 32);   // warp stride = 32 float4 = 128 floats
    }

    float s0 = 0.0f, s1 = 0.0f;
    #pragma unroll
    for (int k = 0; k < 8; k++) {
        float4 w = w4[lane + 32 * k];
        s0 = fmaf(v[k].x, w.x, s0);
        s1 = fmaf(v[k].y, w.y, s1);
        s0 = fmaf(v[k].z, w.z, s0);
        s1 = fmaf(v[k].w, w.w, s1);
    }
    return s0 + s1;
}

__global__ __launch_bounds__(THREADS, 5)
void fractal_dim_kernel(const float* __restrict__ in, float* __restrict__ out) {
    __shared__ float4 w4[L / 4];   // w4[i] = {1/(4i+1), ..., 1/(4i+4)}

    const int t = threadIdx.x;
    {
        int base = t * 4;
        float4 w;
        w.x = 1.0f / (float)(base + 1);
        w.y = 1.0f / (float)(base + 2);
        w.z = 1.0f / (float)(base + 3);
        w.w = 1.0f / (float)(base + 4);
        w4[t] = w;
    }
    __syncthreads();

    const int lane = t & 31;
    const int wid  = t >> 5;

    // Balanced contiguous split: block range, then warp range within it.
    const int bstart = (int)((long long)blockIdx.x       * ROWS / GRID);
    const int bend   = (int)((long long)(blockIdx.x + 1) * ROWS / GRID);
    const int n      = bend - bstart;
    const int wstart = bstart + (int)((long long)wid       * n / 8);
    const int wend   = bstart + (int)((long long)(wid + 1) * n / 8);

    int row = wstart;

    // ── Paired rows: 6-shuffle joint reduction ──
    for (; row + 1 < wend; row += 2) {
        float sA = row_partial(in, w4, lane, row);
        float sB = row_partial(in, w4, lane, row + 1);

        // Cross-half exchange, then select A into lanes 0-15, B into 16-31.
        float xa = sA + __shfl_xor_sync(0xffffffffu, sA, 16);
        float xb = sB + __shfl_xor_sync(0xffffffffu, sB, 16);
        float z  = (lane < 16) ? xa : xb;

        #pragma unroll
        for (int off = 8; off > 0; off >>= 1) {
            z += __shfl_xor_sync(0xffffffffu, z, off);
        }

        if (lane == 0)  out[row]     = z;   // full sum of row A
        if (lane == 16) out[row + 1] = z;   // full sum of row B
    }

    // ── Possible odd final row ──
    if (row < wend) {
        float s = row_partial(in, w4, lane, row);
        #pragma unroll
        for (int off = 16; off > 0; off >>= 1) {
            s += __shfl_xor_sync(0xffffffffu, s, off);
        }
        if (lane == 0) out[row] = s;
    }
}

extern "C" void kernel_launch(void* const* d_in, const int* in_sizes, int n_in,
                              void* d_out, int out_size) {
    const float* in  = (const float*)d_in[0];
    float*       out = (float*)d_out;
    fractal_dim_kernel<<<GRID, THREADS>>>(in, out);
}